// round 11
// baseline (speedup 1.0000x reference)
#include <cuda_runtime.h>
#include <cuda_bf16.h>
#include <math.h>
#include <stdint.h>

// ---------------- problem constants ----------------
#define TT   4096
#define HH   2048
#define EE   64
#define MM   1408
#define MSS  2816
#define KK   6
#define CC   768
#define NGG  8
#define TGG  3
#define NPAIR (TT*KK)        // 24576

// ---------------- device scratch ----------------
__device__ int   g_topk_i[NPAIR];
__device__ float g_topk_w[NPAIR];
__device__ int   g_cnt[EE];
__device__ int   g_lists[EE*CC];
__device__ float g_gbuf[(size_t)NPAIR*MM];
__device__ float g_ubuf[(size_t)NPAIR*MM];
__device__ float g_hbuf[(size_t)NPAIR*MM];
__device__ float g_outb[(size_t)NPAIR*HH];
__device__ float g_gs[(size_t)TT*MSS];
__device__ float g_us[(size_t)TT*MSS];
__device__ float g_hs[(size_t)TT*MSS];
__device__ float g_ys[(size_t)TT*HH];

// ---------------- gate ----------------
__global__ void gate_kernel(const float* __restrict__ x,
                            const float* __restrict__ gw,
                            int* __restrict__ ti, float* __restrict__ tw)
{
    int t = blockIdx.x;
    __shared__ float xs[HH];
    __shared__ float sc[EE];
    for (int i = threadIdx.x; i < HH; i += 64) xs[i] = x[(size_t)t*HH + i];
    __syncthreads();
    {
        int e = threadIdx.x;
        const float* w = gw + (size_t)e * HH;
        float acc = 0.f;
        #pragma unroll 8
        for (int h = 0; h < HH; ++h) acc = fmaf(xs[h], w[h], acc);
        sc[e] = acc;
    }
    __syncthreads();
    if (threadIdx.x == 0) {
        float mx = sc[0];
        for (int e = 1; e < EE; ++e) mx = fmaxf(mx, sc[e]);
        float sum = 0.f;
        for (int e = 0; e < EE; ++e) { float v = expf(sc[e] - mx); sc[e] = v; sum += v; }
        float inv = 1.f / sum;
        for (int e = 0; e < EE; ++e) sc[e] *= inv;
        float gs[NGG];
        for (int g = 0; g < NGG; ++g) {
            float m = sc[g*8];
            for (int j = 1; j < 8; ++j) m = fmaxf(m, sc[g*8 + j]);
            gs[g] = m;
        }
        unsigned gsel = 0;
        for (int it = 0; it < TGG; ++it) {
            int best = -1; float bv = -1e30f;
            for (int g = 0; g < NGG; ++g)
                if (!((gsel >> g) & 1u) && gs[g] > bv) { bv = gs[g]; best = g; }
            gsel |= 1u << best;
        }
        unsigned long long used = 0ull;
        for (int kk = 0; kk < KK; ++kk) {
            int best = -1; float bv = -1e30f;
            for (int e = 0; e < EE; ++e) {
                if (!((gsel >> (e >> 3)) & 1u)) continue;
                if ((used >> e) & 1ull) continue;
                if (sc[e] > bv) { bv = sc[e]; best = e; }
            }
            used |= 1ull << best;
            ti[t*KK + kk] = best;
            tw[t*KK + kk] = sc[best];
        }
    }
}

__global__ void zero_cnt_kernel() { if (threadIdx.x < EE) g_cnt[threadIdx.x] = 0; }

__global__ void dispatch_kernel(const int* __restrict__ ti)
{
    int p = blockIdx.x * blockDim.x + threadIdx.x;
    if (p >= NPAIR) return;
    int e = ti[p];
    int r = atomicAdd(&g_cnt[e], 1);
    if (r < CC) g_lists[e*CC + r] = p;
}

// ---------------- swiglu (fp32 out) ----------------
__global__ void swiglu_kernel(const float* __restrict__ g,
                              const float* __restrict__ u,
                              float* __restrict__ h, size_t n4)
{
    size_t i = (size_t)blockIdx.x * blockDim.x + threadIdx.x;
    size_t stride = (size_t)gridDim.x * blockDim.x;
    for (; i < n4; i += stride) {
        float4 gv = ((const float4*)g)[i];
        float4 uv = ((const float4*)u)[i];
        float4 r;
        r.x = (gv.x / (1.f + expf(-gv.x))) * uv.x;
        r.y = (gv.y / (1.f + expf(-gv.y))) * uv.y;
        r.z = (gv.z / (1.f + expf(-gv.z))) * uv.z;
        r.w = (gv.w / (1.f + expf(-gv.w))) * uv.w;
        ((float4*)h)[i] = r;
    }
}

// ======================= single-pass tf32 MMA GEMM =========
// CTA 128x128, k-chunk 32 (4 k-steps of 8), 128 threads (4 warps of 64x64),
// 2-stage smem, fused fp32->tf32 in the loader, 2 CTAs/SM.

#define LDSM4(R, addr) asm volatile( \
    "ldmatrix.sync.aligned.m8n8.x4.shared.b16 {%0,%1,%2,%3},[%4];" \
    : "=r"((R)[0]), "=r"((R)[1]), "=r"((R)[2]), "=r"((R)[3]) : "r"(addr))
#define MMAT(C, A, B) asm volatile( \
    "mma.sync.aligned.m16n8k8.row.col.f32.tf32.tf32.f32 " \
    "{%0,%1,%2,%3},{%4,%5,%6,%7},{%8,%9},{%0,%1,%2,%3};" \
    : "+f"((C)[0]), "+f"((C)[1]), "+f"((C)[2]), "+f"((C)[3]) \
    : "r"((A)[0]), "r"((A)[1]), "r"((A)[2]), "r"((A)[3]), "r"((B)[0]), "r"((B)[1]))

// row pitch 144B (32 fp32 + 16B pad -> conflict-free ldmatrix), A at 0, B at 18432
#define PITCH   144
#define B_BASE  18432
#define STAGE_B 36864
#define SMEM_TOT (2*STAGE_B + 1024)

__device__ __forceinline__ uint32_t f2tf(float x){
    uint32_t u; asm("cvt.rna.tf32.f32 %0, %1;" : "=r"(u) : "f"(x)); return u;
}
__device__ __forceinline__ uint4 cvt4(float4 v){
    return make_uint4(f2tf(v.x), f2tf(v.y), f2tf(v.z), f2tf(v.w));
}

template<bool GATHER>
__global__ void __launch_bounds__(128, 2)
fg_gemm(const float* __restrict__ A,
        const float* __restrict__ Bg,
        float* __restrict__ Out,
        int Kd, int adiv, long long bstride, int ldo, int nrows_fixed)
{
    extern __shared__ char smem[];
    const int e = blockIdx.z;
    int nrows; const int* mylist = nullptr;
    if (GATHER){ nrows = min(g_cnt[e], CC); mylist = &g_lists[e*CC]; }
    else nrows = nrows_fixed;
    const int m0 = blockIdx.y*128;
    if (m0 >= nrows) return;
    const int n0 = blockIdx.x*128;
    const float* B = Bg + (size_t)e*bstride;

    int* rowA = (int*)(smem + 2*STAGE_B);
    int* rowO = (int*)(smem + 2*STAGE_B + 512);
    const int tid = threadIdx.x;
    {
        int r = m0 + tid;
        if (r < nrows){
            if (GATHER){ int p = mylist[r]; rowA[tid] = p/adiv; rowO[tid] = p; }
            else       { rowA[tid] = r;      rowO[tid] = r; }
        } else { rowA[tid] = -1; rowO[tid] = -1; }
    }
    __syncthreads();

    // loaders: thread t owns A row t and B row t (32 floats each, 2 phases of 16)
    int ra = rowA[tid]; if (ra < 0) ra = 0;
    const float* pa = A + (size_t)ra*Kd;
    const float* pb = B + (size_t)(n0 + tid)*Kd;
    char* sa = smem + tid*PITCH;
    char* sb = smem + B_BASE + tid*PITCH;

    float4 s0, s1, s2, s3;     // shared 16-float staging
    auto ldg16 = [&](const float* p, int kf){
        s0 = *(const float4*)(p + kf);
        s1 = *(const float4*)(p + kf + 4);
        s2 = *(const float4*)(p + kf + 8);
        s3 = *(const float4*)(p + kf + 12);
    };
    auto sts16 = [&](char* d, int buf, int half){
        char* dd = d + buf*STAGE_B + half*64;
        *(uint4*)(dd)      = cvt4(s0);
        *(uint4*)(dd + 16) = cvt4(s1);
        *(uint4*)(dd + 32) = cvt4(s2);
        *(uint4*)(dd + 48) = cvt4(s3);
    };

    const int lane = tid & 31;
    const int wid  = tid >> 5;
    const int wm = (wid & 1) * 64;       // warp tile 64x64
    const int wn = (wid >> 1) * 64;

    float acc[4][8][4];
    #pragma unroll
    for (int i = 0; i < 4; ++i)
        #pragma unroll
        for (int j = 0; j < 8; ++j)
            #pragma unroll
            for (int c = 0; c < 4; ++c) acc[i][j][c] = 0.f;

    const uint32_t smem_u = (uint32_t)__cvta_generic_to_shared(smem);
    const uint32_t aoff = (uint32_t)((wm + (lane & 15)) * PITCH + (lane >> 4) * 16);
    const uint32_t boff = (uint32_t)(B_BASE
        + (wn + (lane & 7) + (lane >> 4) * 8) * PITCH + ((lane >> 3) & 1) * 16);

    // one k-step (k=8): 8x LDSM4 + 32 MMA
    auto mma_ks = [&](uint32_t b, int ks){
        const uint32_t ko = ks * 32;
        uint32_t af[4][4], bf[4][4];
        #pragma unroll
        for (int j = 0; j < 4; ++j)
            LDSM4(bf[j], b + boff + j*2304 + ko);      // n-tile pair j (16 rows*144B)
        #pragma unroll
        for (int mi = 0; mi < 4; ++mi)
            LDSM4(af[mi], b + aoff + mi*2304 + ko);
        #pragma unroll
        for (int mi = 0; mi < 4; ++mi)
            #pragma unroll
            for (int ni = 0; ni < 8; ++ni)
                MMAT(acc[mi][ni], af[mi], (&bf[ni>>1][(ni&1)*2]));
    };

    const int KT = Kd / 32;
    // prologue: fill stage 0
    ldg16(pa, 0);  sts16(sa, 0, 0);
    ldg16(pa, 16); sts16(sa, 0, 1);
    ldg16(pb, 0);  sts16(sb, 0, 0);
    ldg16(pb, 16); sts16(sb, 0, 1);

    for (int kt = 0; kt < KT; ++kt){
        __syncthreads();
        const uint32_t b = smem_u + (kt & 1) * STAGE_B;
        const int nb = (kt + 1) & 1;
        const bool more = (kt + 1 < KT);
        const int kn = (kt + 1) * 32;
        if (more) ldg16(pa, kn);
        mma_ks(b, 0);
        if (more){ sts16(sa, nb, 0); ldg16(pa, kn + 16); }
        mma_ks(b, 1);
        if (more){ sts16(sa, nb, 1); ldg16(pb, kn); }
        mma_ks(b, 2);
        if (more){ sts16(sb, nb, 0); ldg16(pb, kn + 16); }
        mma_ks(b, 3);
        if (more) sts16(sb, nb, 1);
    }

    // epilogue
    const int g4 = lane >> 2, tig = lane & 3;
    #pragma unroll
    for (int mi = 0; mi < 4; ++mi){
        int r0 = wm + mi*16 + g4;
        int r1 = r0 + 8;
        int o0 = rowO[r0], o1 = rowO[r1];
        #pragma unroll
        for (int ni = 0; ni < 8; ++ni){
            int cc = n0 + wn + ni*8 + tig*2;
            if (o0 >= 0)
                *(float2*)(Out + (size_t)o0*ldo + cc) = make_float2(acc[mi][ni][0], acc[mi][ni][1]);
            if (o1 >= 0)
                *(float2*)(Out + (size_t)o1*ldo + cc) = make_float2(acc[mi][ni][2], acc[mi][ni][3]);
        }
    }
}

// ---------------- combine ----------------
__global__ void combine_kernel(const float* __restrict__ ob,
                               const float* __restrict__ ys,
                               const float* __restrict__ tw,
                               float* __restrict__ y)
{
    int t = blockIdx.x;
    for (int c = threadIdx.x; c < HH; c += blockDim.x) {
        float acc = ys[(size_t)t*HH + c];
        #pragma unroll
        for (int k = 0; k < KK; ++k) {
            int p = t*KK + k;
            acc = fmaf(tw[p], ob[(size_t)p*HH + c], acc);
        }
        y[(size_t)t*HH + c] = acc;
    }
}

// ---------------- launch ----------------
extern "C" void kernel_launch(void* const* d_in, const int* in_sizes, int n_in,
                              void* d_out, int out_size)
{
    const float* x  = (const float*)d_in[0];
    const float* gw = (const float*)d_in[1];
    const float* Wg = (const float*)d_in[2];
    const float* Wu = (const float*)d_in[3];
    const float* Wd = (const float*)d_in[4];
    const float* Sg = (const float*)d_in[5];
    const float* Su = (const float*)d_in[6];
    const float* Sd = (const float*)d_in[7];
    float* y = (float*)d_out;

    void *p_ti, *p_tw, *p_g, *p_u, *p_h, *p_ob, *p_gs, *p_us, *p_hs, *p_ys;
    cudaGetSymbolAddress(&p_ti, g_topk_i);  cudaGetSymbolAddress(&p_tw, g_topk_w);
    cudaGetSymbolAddress(&p_g,  g_gbuf);    cudaGetSymbolAddress(&p_u,  g_ubuf);
    cudaGetSymbolAddress(&p_h,  g_hbuf);    cudaGetSymbolAddress(&p_ob, g_outb);
    cudaGetSymbolAddress(&p_gs, g_gs);      cudaGetSymbolAddress(&p_us, g_us);
    cudaGetSymbolAddress(&p_hs, g_hs);      cudaGetSymbolAddress(&p_ys, g_ys);

    cudaFuncSetAttribute(fg_gemm<true>,  cudaFuncAttributeMaxDynamicSharedMemorySize, SMEM_TOT);
    cudaFuncSetAttribute(fg_gemm<false>, cudaFuncAttributeMaxDynamicSharedMemorySize, SMEM_TOT);

    // 1) gate + dispatch
    gate_kernel<<<TT, 64>>>(x, gw, (int*)p_ti, (float*)p_tw);
    zero_cnt_kernel<<<1, 64>>>();
    dispatch_kernel<<<(NPAIR + 255)/256, 256>>>((const int*)p_ti);

    // 2) routed GEMM1: g and u (A = gathered x rows fp32, K = HH)
    fg_gemm<true><<<dim3(MM/128, CC/128, EE), 128, SMEM_TOT>>>(
        x, Wg, (float*)p_g, HH, KK, (long long)MM*HH, MM, 0);
    fg_gemm<true><<<dim3(MM/128, CC/128, EE), 128, SMEM_TOT>>>(
        x, Wu, (float*)p_u, HH, KK, (long long)MM*HH, MM, 0);

    // 3) swiglu -> h (fp32)
    {
        size_t n4 = (size_t)NPAIR*MM/4;
        swiglu_kernel<<<(int)((n4 + 255)/256), 256>>>((const float*)p_g, (const float*)p_u,
                                                      (float*)p_h, n4);
    }

    // 4) routed GEMM2 (Wd): A = h rows by pair id, K = MM
    fg_gemm<true><<<dim3(HH/128, CC/128, EE), 128, SMEM_TOT>>>(
        (const float*)p_h, Wd, (float*)p_ob, MM, 1, (long long)HH*MM, HH, 0);

    // 5) shared expert g,u (K = HH)
    fg_gemm<false><<<dim3(MSS/128, TT/128, 1), 128, SMEM_TOT>>>(
        x, Sg, (float*)p_gs, HH, 1, 0LL, MSS, TT);
    fg_gemm<false><<<dim3(MSS/128, TT/128, 1), 128, SMEM_TOT>>>(
        x, Su, (float*)p_us, HH, 1, 0LL, MSS, TT);

    // 6) shared swiglu
    {
        size_t n4 = (size_t)TT*MSS/4;
        swiglu_kernel<<<(int)((n4 + 255)/256), 256>>>((const float*)p_gs, (const float*)p_us,
                                                      (float*)p_hs, n4);
    }

    // 7) shared GEMM2 (Sd, K = MSS)
    fg_gemm<false><<<dim3(HH/128, TT/128, 1), 128, SMEM_TOT>>>(
        (const float*)p_hs, Sd, (float*)p_ys, MSS, 1, 0LL, HH, TT);

    // 8) combine
    combine_kernel<<<TT, 256>>>((const float*)p_ob, (const float*)p_ys,
                                (const float*)p_tw, y);
}

// round 12
// speedup vs baseline: 1.1161x; 1.1161x over previous
#include <cuda_runtime.h>
#include <cuda_bf16.h>
#include <math.h>
#include <stdint.h>

// ---------------- problem constants ----------------
#define TT   4096
#define HH   2048
#define EE   64
#define MM   1408
#define MSS  2816
#define KK   6
#define CC   768
#define NGG  8
#define TGG  3
#define NPAIR (TT*KK)        // 24576

// ---------------- device scratch ----------------
__device__ int   g_topk_i[NPAIR];
__device__ float g_topk_w[NPAIR];
__device__ int   g_cnt[EE];
__device__ int   g_lists[EE*CC];
__device__ float g_gbuf[(size_t)NPAIR*MM];
__device__ float g_ubuf[(size_t)NPAIR*MM];
__device__ float g_hbuf[(size_t)NPAIR*MM];
__device__ float g_outb[(size_t)NPAIR*HH];
__device__ float g_gs[(size_t)TT*MSS];
__device__ float g_us[(size_t)TT*MSS];
__device__ float g_hs[(size_t)TT*MSS];
__device__ float g_ys[(size_t)TT*HH];

// ---------------- gate ----------------
__global__ void gate_kernel(const float* __restrict__ x,
                            const float* __restrict__ gw,
                            int* __restrict__ ti, float* __restrict__ tw)
{
    int t = blockIdx.x;
    __shared__ float xs[HH];
    __shared__ float sc[EE];
    for (int i = threadIdx.x; i < HH; i += 64) xs[i] = x[(size_t)t*HH + i];
    __syncthreads();
    {
        int e = threadIdx.x;
        const float* w = gw + (size_t)e * HH;
        float acc = 0.f;
        #pragma unroll 8
        for (int h = 0; h < HH; ++h) acc = fmaf(xs[h], w[h], acc);
        sc[e] = acc;
    }
    __syncthreads();
    if (threadIdx.x == 0) {
        float mx = sc[0];
        for (int e = 1; e < EE; ++e) mx = fmaxf(mx, sc[e]);
        float sum = 0.f;
        for (int e = 0; e < EE; ++e) { float v = expf(sc[e] - mx); sc[e] = v; sum += v; }
        float inv = 1.f / sum;
        for (int e = 0; e < EE; ++e) sc[e] *= inv;
        float gs[NGG];
        for (int g = 0; g < NGG; ++g) {
            float m = sc[g*8];
            for (int j = 1; j < 8; ++j) m = fmaxf(m, sc[g*8 + j]);
            gs[g] = m;
        }
        unsigned gsel = 0;
        for (int it = 0; it < TGG; ++it) {
            int best = -1; float bv = -1e30f;
            for (int g = 0; g < NGG; ++g)
                if (!((gsel >> g) & 1u) && gs[g] > bv) { bv = gs[g]; best = g; }
            gsel |= 1u << best;
        }
        unsigned long long used = 0ull;
        for (int kk = 0; kk < KK; ++kk) {
            int best = -1; float bv = -1e30f;
            for (int e = 0; e < EE; ++e) {
                if (!((gsel >> (e >> 3)) & 1u)) continue;
                if ((used >> e) & 1ull) continue;
                if (sc[e] > bv) { bv = sc[e]; best = e; }
            }
            used |= 1ull << best;
            ti[t*KK + kk] = best;
            tw[t*KK + kk] = sc[best];
        }
    }
}

__global__ void zero_cnt_kernel() { if (threadIdx.x < EE) g_cnt[threadIdx.x] = 0; }

__global__ void dispatch_kernel(const int* __restrict__ ti)
{
    int p = blockIdx.x * blockDim.x + threadIdx.x;
    if (p >= NPAIR) return;
    int e = ti[p];
    int r = atomicAdd(&g_cnt[e], 1);
    if (r < CC) g_lists[e*CC + r] = p;
}

// ---------------- swiglu (fp32 out) ----------------
__global__ void swiglu_kernel(const float* __restrict__ g,
                              const float* __restrict__ u,
                              float* __restrict__ h, size_t n4)
{
    size_t i = (size_t)blockIdx.x * blockDim.x + threadIdx.x;
    size_t stride = (size_t)gridDim.x * blockDim.x;
    for (; i < n4; i += stride) {
        float4 gv = ((const float4*)g)[i];
        float4 uv = ((const float4*)u)[i];
        float4 r;
        r.x = (gv.x / (1.f + expf(-gv.x))) * uv.x;
        r.y = (gv.y / (1.f + expf(-gv.y))) * uv.y;
        r.z = (gv.z / (1.f + expf(-gv.z))) * uv.z;
        r.w = (gv.w / (1.f + expf(-gv.w))) * uv.w;
        ((float4*)h)[i] = r;
    }
}

// ======================= single-pass tf32 MMA GEMM (cp.async) =========
// CTA 128x128, k-chunk 32 (4 k-steps of 8), 256 threads (8 warps of 64x32),
// 2-stage cp.async pipeline (L1 bypass), fragment-side fp32->tf32, 2 CTAs/SM.

#define LDSM4(R, addr) asm volatile( \
    "ldmatrix.sync.aligned.m8n8.x4.shared.b16 {%0,%1,%2,%3},[%4];" \
    : "=r"((R)[0]), "=r"((R)[1]), "=r"((R)[2]), "=r"((R)[3]) : "r"(addr))
#define MMAT(C, A, B) asm volatile( \
    "mma.sync.aligned.m16n8k8.row.col.f32.tf32.tf32.f32 " \
    "{%0,%1,%2,%3},{%4,%5,%6,%7},{%8,%9},{%0,%1,%2,%3};" \
    : "+f"((C)[0]), "+f"((C)[1]), "+f"((C)[2]), "+f"((C)[3]) \
    : "r"((A)[0]), "r"((A)[1]), "r"((A)[2]), "r"((A)[3]), "r"((B)[0]), "r"((B)[1]))

// row pitch 144B (32 fp32 + 16B pad -> conflict-free ldmatrix), A at 0, B at 18432
#define PITCH   144
#define B_BASE  18432
#define STAGE_B 36864
#define SMEM_TOT (2*STAGE_B + 1024)

__device__ __forceinline__ uint32_t tfr(uint32_t x){
    uint32_t r; asm("cvt.rna.tf32.f32 %0, %1;" : "=r"(r) : "f"(__uint_as_float(x)));
    return r;
}
__device__ __forceinline__ void cp16z(uint32_t dst, const void* src, int sz){
    asm volatile("cp.async.cg.shared.global [%0], [%1], 16, %2;"
                 :: "r"(dst), "l"(src), "r"(sz));
}

template<bool GATHER>
__global__ void __launch_bounds__(256, 2)
fg_gemm(const float* __restrict__ A,
        const float* __restrict__ Bg,
        float* __restrict__ Out,
        int Kd, int adiv, long long bstride, int ldo, int nrows_fixed)
{
    extern __shared__ char smem[];
    const int e = blockIdx.z;
    int nrows; const int* mylist = nullptr;
    if (GATHER){ nrows = min(g_cnt[e], CC); mylist = &g_lists[e*CC]; }
    else nrows = nrows_fixed;
    const int m0 = blockIdx.y*128;
    if (m0 >= nrows) return;
    const int n0 = blockIdx.x*128;
    const float* B = Bg + (size_t)e*bstride;

    int* rowA = (int*)(smem + 2*STAGE_B);
    int* rowO = (int*)(smem + 2*STAGE_B + 512);
    const int tid = threadIdx.x;
    if (tid < 128){
        int r = m0 + tid;
        if (r < nrows){
            if (GATHER){ int p = mylist[r]; rowA[tid] = p/adiv; rowO[tid] = p; }
            else       { rowA[tid] = r;      rowO[tid] = r; }
        } else { rowA[tid] = -1; rowO[tid] = -1; }
    }
    __syncthreads();

    const uint32_t smem_u = (uint32_t)__cvta_generic_to_shared(smem);

    // loaders: lrow = tid>>1 (0..127), half = tid&1 (16 floats each)
    const int lrow = tid >> 1, half = tid & 1;
    int ra = rowA[lrow];
    const int szA = (ra < 0) ? 0 : 16;
    if (ra < 0) ra = 0;
    const float* pa = A + (size_t)ra*Kd + half*16;
    const float* pb = B + (size_t)(n0 + lrow)*Kd + half*16;
    const uint32_t sa_u = smem_u + lrow*PITCH + half*64;
    const uint32_t sb_u = smem_u + B_BASE + lrow*PITCH + half*64;

    auto load_chunk = [&](int buf, int kt){
        const int k0 = kt*32;
        const uint32_t da = sa_u + buf*STAGE_B;
        const uint32_t db = sb_u + buf*STAGE_B;
        const float* qa = pa + k0;
        const float* qb = pb + k0;
        #pragma unroll
        for (int j = 0; j < 4; ++j){
            cp16z(da + j*16, qa + j*4, szA);
            cp16z(db + j*16, qb + j*4, 16);
        }
        asm volatile("cp.async.commit_group;" ::);
    };

    const int lane = tid & 31;
    const int wid  = tid >> 5;
    const int wm = (wid & 1) * 64;       // warp tile 64x32
    const int wn = (wid >> 1) * 32;

    float acc[4][4][4];
    #pragma unroll
    for (int i = 0; i < 4; ++i)
        #pragma unroll
        for (int j = 0; j < 4; ++j)
            #pragma unroll
            for (int c = 0; c < 4; ++c) acc[i][j][c] = 0.f;

    const uint32_t aoff = (uint32_t)((wm + (lane & 15)) * PITCH + (lane >> 4) * 16);
    const uint32_t boff = (uint32_t)(B_BASE
        + (wn + (lane & 7) + (lane >> 4) * 8) * PITCH + ((lane >> 3) & 1) * 16);

    // one k-step (k=8): 6x LDSM4 + 24 cvt + 16 MMA
    auto mma_ks = [&](uint32_t b, int ks){
        const uint32_t ko = ks * 32;
        uint32_t af[4][4], bf[2][4];
        LDSM4(bf[0], b + boff + ko);            // n-tiles 0,1
        LDSM4(bf[1], b + boff + 2304 + ko);     // n-tiles 2,3
        #pragma unroll
        for (int mi = 0; mi < 4; ++mi)
            LDSM4(af[mi], b + aoff + mi*2304 + ko);
        #pragma unroll
        for (int mi = 0; mi < 4; ++mi)
            #pragma unroll
            for (int j = 0; j < 4; ++j) af[mi][j] = tfr(af[mi][j]);
        #pragma unroll
        for (int i = 0; i < 2; ++i)
            #pragma unroll
            for (int j = 0; j < 4; ++j) bf[i][j] = tfr(bf[i][j]);
        #pragma unroll
        for (int mi = 0; mi < 4; ++mi)
            #pragma unroll
            for (int ni = 0; ni < 4; ++ni)
                MMAT(acc[mi][ni], af[mi], (&bf[ni>>1][(ni&1)*2]));
    };

    const int KT = Kd / 32;
    // prologue: issue stages 0 and 1
    load_chunk(0, 0);
    if (KT > 1) load_chunk(1, 1);

    for (int kt = 0; kt < KT; ++kt){
        if (kt + 1 < KT) asm volatile("cp.async.wait_group 1;" ::);
        else             asm volatile("cp.async.wait_group 0;" ::);
        __syncthreads();
        const uint32_t b = smem_u + (kt & 1) * STAGE_B;
        mma_ks(b, 0);
        mma_ks(b, 1);
        mma_ks(b, 2);
        mma_ks(b, 3);
        if (kt + 2 < KT){
            __syncthreads();
            load_chunk(kt & 1, kt + 2);
        }
    }

    // epilogue
    const int g4 = lane >> 2, tig = lane & 3;
    #pragma unroll
    for (int mi = 0; mi < 4; ++mi){
        int r0 = wm + mi*16 + g4;
        int r1 = r0 + 8;
        int o0 = rowO[r0], o1 = rowO[r1];
        #pragma unroll
        for (int ni = 0; ni < 4; ++ni){
            int cc = n0 + wn + ni*8 + tig*2;
            if (o0 >= 0)
                *(float2*)(Out + (size_t)o0*ldo + cc) = make_float2(acc[mi][ni][0], acc[mi][ni][1]);
            if (o1 >= 0)
                *(float2*)(Out + (size_t)o1*ldo + cc) = make_float2(acc[mi][ni][2], acc[mi][ni][3]);
        }
    }
}

// ---------------- combine ----------------
__global__ void combine_kernel(const float* __restrict__ ob,
                               const float* __restrict__ ys,
                               const float* __restrict__ tw,
                               float* __restrict__ y)
{
    int t = blockIdx.x;
    for (int c = threadIdx.x; c < HH; c += blockDim.x) {
        float acc = ys[(size_t)t*HH + c];
        #pragma unroll
        for (int k = 0; k < KK; ++k) {
            int p = t*KK + k;
            acc = fmaf(tw[p], ob[(size_t)p*HH + c], acc);
        }
        y[(size_t)t*HH + c] = acc;
    }
}

// ---------------- launch ----------------
extern "C" void kernel_launch(void* const* d_in, const int* in_sizes, int n_in,
                              void* d_out, int out_size)
{
    const float* x  = (const float*)d_in[0];
    const float* gw = (const float*)d_in[1];
    const float* Wg = (const float*)d_in[2];
    const float* Wu = (const float*)d_in[3];
    const float* Wd = (const float*)d_in[4];
    const float* Sg = (const float*)d_in[5];
    const float* Su = (const float*)d_in[6];
    const float* Sd = (const float*)d_in[7];
    float* y = (float*)d_out;

    void *p_ti, *p_tw, *p_g, *p_u, *p_h, *p_ob, *p_gs, *p_us, *p_hs, *p_ys;
    cudaGetSymbolAddress(&p_ti, g_topk_i);  cudaGetSymbolAddress(&p_tw, g_topk_w);
    cudaGetSymbolAddress(&p_g,  g_gbuf);    cudaGetSymbolAddress(&p_u,  g_ubuf);
    cudaGetSymbolAddress(&p_h,  g_hbuf);    cudaGetSymbolAddress(&p_ob, g_outb);
    cudaGetSymbolAddress(&p_gs, g_gs);      cudaGetSymbolAddress(&p_us, g_us);
    cudaGetSymbolAddress(&p_hs, g_hs);      cudaGetSymbolAddress(&p_ys, g_ys);

    cudaFuncSetAttribute(fg_gemm<true>,  cudaFuncAttributeMaxDynamicSharedMemorySize, SMEM_TOT);
    cudaFuncSetAttribute(fg_gemm<false>, cudaFuncAttributeMaxDynamicSharedMemorySize, SMEM_TOT);

    // 1) gate + dispatch
    gate_kernel<<<TT, 64>>>(x, gw, (int*)p_ti, (float*)p_tw);
    zero_cnt_kernel<<<1, 64>>>();
    dispatch_kernel<<<(NPAIR + 255)/256, 256>>>((const int*)p_ti);

    // 2) routed GEMM1: g and u (A = gathered x rows fp32, K = HH)
    fg_gemm<true><<<dim3(MM/128, CC/128, EE), 256, SMEM_TOT>>>(
        x, Wg, (float*)p_g, HH, KK, (long long)MM*HH, MM, 0);
    fg_gemm<true><<<dim3(MM/128, CC/128, EE), 256, SMEM_TOT>>>(
        x, Wu, (float*)p_u, HH, KK, (long long)MM*HH, MM, 0);

    // 3) swiglu -> h (fp32)
    {
        size_t n4 = (size_t)NPAIR*MM/4;
        swiglu_kernel<<<(int)((n4 + 255)/256), 256>>>((const float*)p_g, (const float*)p_u,
                                                      (float*)p_h, n4);
    }

    // 4) routed GEMM2 (Wd): A = h rows by pair id, K = MM
    fg_gemm<true><<<dim3(HH/128, CC/128, EE), 256, SMEM_TOT>>>(
        (const float*)p_h, Wd, (float*)p_ob, MM, 1, (long long)HH*MM, HH, 0);

    // 5) shared expert g,u (K = HH)
    fg_gemm<false><<<dim3(MSS/128, TT/128, 1), 256, SMEM_TOT>>>(
        x, Sg, (float*)p_gs, HH, 1, 0LL, MSS, TT);
    fg_gemm<false><<<dim3(MSS/128, TT/128, 1), 256, SMEM_TOT>>>(
        x, Su, (float*)p_us, HH, 1, 0LL, MSS, TT);

    // 6) shared swiglu
    {
        size_t n4 = (size_t)TT*MSS/4;
        swiglu_kernel<<<(int)((n4 + 255)/256), 256>>>((const float*)p_gs, (const float*)p_us,
                                                      (float*)p_hs, n4);
    }

    // 7) shared GEMM2 (Sd, K = MSS)
    fg_gemm<false><<<dim3(HH/128, TT/128, 1), 256, SMEM_TOT>>>(
        (const float*)p_hs, Sd, (float*)p_ys, MSS, 1, 0LL, HH, TT);

    // 8) combine
    combine_kernel<<<TT, 256>>>((const float*)p_ob, (const float*)p_ys,
                                (const float*)p_tw, y);
}

// round 13
// speedup vs baseline: 1.1366x; 1.0184x over previous
#include <cuda_runtime.h>
#include <cuda_bf16.h>
#include <math.h>
#include <stdint.h>

// ---------------- problem constants ----------------
#define TT   4096
#define HH   2048
#define EE   64
#define MM   1408
#define MSS  2816
#define KK   6
#define CC   768
#define NGG  8
#define TGG  3
#define NPAIR (TT*KK)        // 24576

// ---------------- device scratch ----------------
__device__ int   g_topk_i[NPAIR];
__device__ float g_topk_w[NPAIR];
__device__ int   g_cnt[EE];
__device__ int   g_lists[EE*CC];
__device__ float g_gbuf[(size_t)NPAIR*MM];
__device__ float g_ubuf[(size_t)NPAIR*MM];
__device__ float g_hbuf[(size_t)NPAIR*MM];
__device__ float g_outb[(size_t)NPAIR*HH];
__device__ float g_gs[(size_t)TT*MSS];
__device__ float g_us[(size_t)TT*MSS];
__device__ float g_hs[(size_t)TT*MSS];
__device__ float g_ys[(size_t)TT*HH];

// ---------------- gate ----------------
__global__ void gate_kernel(const float* __restrict__ x,
                            const float* __restrict__ gw,
                            int* __restrict__ ti, float* __restrict__ tw)
{
    int t = blockIdx.x;
    __shared__ float xs[HH];
    __shared__ float sc[EE];
    for (int i = threadIdx.x; i < HH; i += 64) xs[i] = x[(size_t)t*HH + i];
    __syncthreads();
    {
        int e = threadIdx.x;
        const float* w = gw + (size_t)e * HH;
        float acc = 0.f;
        #pragma unroll 8
        for (int h = 0; h < HH; ++h) acc = fmaf(xs[h], w[h], acc);
        sc[e] = acc;
    }
    __syncthreads();
    if (threadIdx.x == 0) {
        float mx = sc[0];
        for (int e = 1; e < EE; ++e) mx = fmaxf(mx, sc[e]);
        float sum = 0.f;
        for (int e = 0; e < EE; ++e) { float v = expf(sc[e] - mx); sc[e] = v; sum += v; }
        float inv = 1.f / sum;
        for (int e = 0; e < EE; ++e) sc[e] *= inv;
        float gs[NGG];
        for (int g = 0; g < NGG; ++g) {
            float m = sc[g*8];
            for (int j = 1; j < 8; ++j) m = fmaxf(m, sc[g*8 + j]);
            gs[g] = m;
        }
        unsigned gsel = 0;
        for (int it = 0; it < TGG; ++it) {
            int best = -1; float bv = -1e30f;
            for (int g = 0; g < NGG; ++g)
                if (!((gsel >> g) & 1u) && gs[g] > bv) { bv = gs[g]; best = g; }
            gsel |= 1u << best;
        }
        unsigned long long used = 0ull;
        for (int kk = 0; kk < KK; ++kk) {
            int best = -1; float bv = -1e30f;
            for (int e = 0; e < EE; ++e) {
                if (!((gsel >> (e >> 3)) & 1u)) continue;
                if ((used >> e) & 1ull) continue;
                if (sc[e] > bv) { bv = sc[e]; best = e; }
            }
            used |= 1ull << best;
            ti[t*KK + kk] = best;
            tw[t*KK + kk] = sc[best];
        }
    }
}

__global__ void zero_cnt_kernel() { if (threadIdx.x < EE) g_cnt[threadIdx.x] = 0; }

__global__ void dispatch_kernel(const int* __restrict__ ti)
{
    int p = blockIdx.x * blockDim.x + threadIdx.x;
    if (p >= NPAIR) return;
    int e = ti[p];
    int r = atomicAdd(&g_cnt[e], 1);
    if (r < CC) g_lists[e*CC + r] = p;
}

// ---------------- swiglu (fp32 out) ----------------
__global__ void swiglu_kernel(const float* __restrict__ g,
                              const float* __restrict__ u,
                              float* __restrict__ h, size_t n4)
{
    size_t i = (size_t)blockIdx.x * blockDim.x + threadIdx.x;
    size_t stride = (size_t)gridDim.x * blockDim.x;
    for (; i < n4; i += stride) {
        float4 gv = ((const float4*)g)[i];
        float4 uv = ((const float4*)u)[i];
        float4 r;
        r.x = (gv.x / (1.f + expf(-gv.x))) * uv.x;
        r.y = (gv.y / (1.f + expf(-gv.y))) * uv.y;
        r.z = (gv.z / (1.f + expf(-gv.z))) * uv.z;
        r.w = (gv.w / (1.f + expf(-gv.w))) * uv.w;
        ((float4*)h)[i] = r;
    }
}

// ======================= single-pass tf32 MMA GEMM (3-stage cp.async) =========
// CTA 128x128, k-chunk 32 (4 k-steps of 8), 256 threads (8 warps of 64x32),
// 3-stage cp.async ring (prefetch issued BEFORE the MMA section), 2 CTAs/SM.

#define LDSM4(R, addr) asm volatile( \
    "ldmatrix.sync.aligned.m8n8.x4.shared.b16 {%0,%1,%2,%3},[%4];" \
    : "=r"((R)[0]), "=r"((R)[1]), "=r"((R)[2]), "=r"((R)[3]) : "r"(addr))
#define MMAT(C, A, B) asm volatile( \
    "mma.sync.aligned.m16n8k8.row.col.f32.tf32.tf32.f32 " \
    "{%0,%1,%2,%3},{%4,%5,%6,%7},{%8,%9},{%0,%1,%2,%3};" \
    : "+f"((C)[0]), "+f"((C)[1]), "+f"((C)[2]), "+f"((C)[3]) \
    : "r"((A)[0]), "r"((A)[1]), "r"((A)[2]), "r"((A)[3]), "r"((B)[0]), "r"((B)[1]))

// row pitch 144B (32 fp32 + 16B pad -> conflict-free ldmatrix), A at 0, B at 18432
#define PITCH   144
#define B_BASE  18432
#define STAGE_B 36864
#define NSTG    3
#define SMEM_TOT (NSTG*STAGE_B + 1024)

__device__ __forceinline__ uint32_t tfr(uint32_t x){
    uint32_t r; asm("cvt.rna.tf32.f32 %0, %1;" : "=r"(r) : "f"(__uint_as_float(x)));
    return r;
}
__device__ __forceinline__ void cp16z(uint32_t dst, const void* src, int sz){
    asm volatile("cp.async.cg.shared.global [%0], [%1], 16, %2;"
                 :: "r"(dst), "l"(src), "r"(sz));
}

template<bool GATHER>
__global__ void __launch_bounds__(256, 2)
fg_gemm(const float* __restrict__ A,
        const float* __restrict__ Bg,
        float* __restrict__ Out,
        int Kd, int adiv, long long bstride, int ldo, int nrows_fixed)
{
    extern __shared__ char smem[];
    const int e = blockIdx.z;
    int nrows; const int* mylist = nullptr;
    if (GATHER){ nrows = min(g_cnt[e], CC); mylist = &g_lists[e*CC]; }
    else nrows = nrows_fixed;
    const int m0 = blockIdx.y*128;
    if (m0 >= nrows) return;
    const int n0 = blockIdx.x*128;
    const float* B = Bg + (size_t)e*bstride;

    int* rowA = (int*)(smem + NSTG*STAGE_B);
    int* rowO = (int*)(smem + NSTG*STAGE_B + 512);
    const int tid = threadIdx.x;
    if (tid < 128){
        int r = m0 + tid;
        if (r < nrows){
            if (GATHER){ int p = mylist[r]; rowA[tid] = p/adiv; rowO[tid] = p; }
            else       { rowA[tid] = r;      rowO[tid] = r; }
        } else { rowA[tid] = -1; rowO[tid] = -1; }
    }
    __syncthreads();

    const uint32_t smem_u = (uint32_t)__cvta_generic_to_shared(smem);

    // loaders: lrow = tid>>1 (0..127), half = tid&1 (16 floats each)
    const int lrow = tid >> 1, half = tid & 1;
    int ra = rowA[lrow];
    const int szA = (ra < 0) ? 0 : 16;
    if (ra < 0) ra = 0;
    const float* pa = A + (size_t)ra*Kd + half*16;
    const float* pb = B + (size_t)(n0 + lrow)*Kd + half*16;
    const uint32_t sa_u = smem_u + lrow*PITCH + half*64;
    const uint32_t sb_u = smem_u + B_BASE + lrow*PITCH + half*64;

    auto load_chunk = [&](int stg, int kt){
        const int k0 = kt*32;
        const uint32_t da = sa_u + stg*STAGE_B;
        const uint32_t db = sb_u + stg*STAGE_B;
        const float* qa = pa + k0;
        const float* qb = pb + k0;
        #pragma unroll
        for (int j = 0; j < 4; ++j){
            cp16z(da + j*16, qa + j*4, szA);
            cp16z(db + j*16, qb + j*4, 16);
        }
        asm volatile("cp.async.commit_group;" ::);
    };

    const int lane = tid & 31;
    const int wid  = tid >> 5;
    const int wm = (wid & 1) * 64;       // warp tile 64x32
    const int wn = (wid >> 1) * 32;

    float acc[4][4][4];
    #pragma unroll
    for (int i = 0; i < 4; ++i)
        #pragma unroll
        for (int j = 0; j < 4; ++j)
            #pragma unroll
            for (int c = 0; c < 4; ++c) acc[i][j][c] = 0.f;

    const uint32_t aoff = (uint32_t)((wm + (lane & 15)) * PITCH + (lane >> 4) * 16);
    const uint32_t boff = (uint32_t)(B_BASE
        + (wn + (lane & 7) + (lane >> 4) * 8) * PITCH + ((lane >> 3) & 1) * 16);

    // one k-step (k=8): 6x LDSM4 + 24 cvt + 16 MMA
    auto mma_ks = [&](uint32_t b, int ks){
        const uint32_t ko = ks * 32;
        uint32_t af[4][4], bf[2][4];
        LDSM4(bf[0], b + boff + ko);            // n-tiles 0,1
        LDSM4(bf[1], b + boff + 2304 + ko);     // n-tiles 2,3
        #pragma unroll
        for (int mi = 0; mi < 4; ++mi)
            LDSM4(af[mi], b + aoff + mi*2304 + ko);
        #pragma unroll
        for (int mi = 0; mi < 4; ++mi)
            #pragma unroll
            for (int j = 0; j < 4; ++j) af[mi][j] = tfr(af[mi][j]);
        #pragma unroll
        for (int i = 0; i < 2; ++i)
            #pragma unroll
            for (int j = 0; j < 4; ++j) bf[i][j] = tfr(bf[i][j]);
        #pragma unroll
        for (int mi = 0; mi < 4; ++mi)
            #pragma unroll
            for (int ni = 0; ni < 4; ++ni)
                MMAT(acc[mi][ni], af[mi], (&bf[ni>>1][(ni&1)*2]));
    };

    const int KT = Kd / 32;
    // prologue: issue stages 0 and 1
    load_chunk(0, 0);
    if (KT > 1) load_chunk(1, 1);

    int stg = 0;
    for (int kt = 0; kt < KT; ++kt){
        if (kt + 1 < KT) asm volatile("cp.async.wait_group 1;" ::);
        else             asm volatile("cp.async.wait_group 0;" ::);
        __syncthreads();
        // issue prefetch for kt+2 into the free stage BEFORE doing the MMA work;
        // safe: that stage was consumed in iteration kt-1, and the barrier above
        // guarantees every warp has finished reading it.
        if (kt + 2 < KT){
            int ns = stg + 2; if (ns >= NSTG) ns -= NSTG;
            load_chunk(ns, kt + 2);
        }
        const uint32_t b = smem_u + stg * STAGE_B;
        mma_ks(b, 0);
        mma_ks(b, 1);
        mma_ks(b, 2);
        mma_ks(b, 3);
        if (++stg == NSTG) stg = 0;
    }

    // epilogue
    const int g4 = lane >> 2, tig = lane & 3;
    #pragma unroll
    for (int mi = 0; mi < 4; ++mi){
        int r0 = wm + mi*16 + g4;
        int r1 = r0 + 8;
        int o0 = rowO[r0], o1 = rowO[r1];
        #pragma unroll
        for (int ni = 0; ni < 4; ++ni){
            int cc = n0 + wn + ni*8 + tig*2;
            if (o0 >= 0)
                *(float2*)(Out + (size_t)o0*ldo + cc) = make_float2(acc[mi][ni][0], acc[mi][ni][1]);
            if (o1 >= 0)
                *(float2*)(Out + (size_t)o1*ldo + cc) = make_float2(acc[mi][ni][2], acc[mi][ni][3]);
        }
    }
}

// ---------------- combine ----------------
__global__ void combine_kernel(const float* __restrict__ ob,
                               const float* __restrict__ ys,
                               const float* __restrict__ tw,
                               float* __restrict__ y)
{
    int t = blockIdx.x;
    for (int c = threadIdx.x; c < HH; c += blockDim.x) {
        float acc = ys[(size_t)t*HH + c];
        #pragma unroll
        for (int k = 0; k < KK; ++k) {
            int p = t*KK + k;
            acc = fmaf(tw[p], ob[(size_t)p*HH + c], acc);
        }
        y[(size_t)t*HH + c] = acc;
    }
}

// ---------------- launch ----------------
extern "C" void kernel_launch(void* const* d_in, const int* in_sizes, int n_in,
                              void* d_out, int out_size)
{
    const float* x  = (const float*)d_in[0];
    const float* gw = (const float*)d_in[1];
    const float* Wg = (const float*)d_in[2];
    const float* Wu = (const float*)d_in[3];
    const float* Wd = (const float*)d_in[4];
    const float* Sg = (const float*)d_in[5];
    const float* Su = (const float*)d_in[6];
    const float* Sd = (const float*)d_in[7];
    float* y = (float*)d_out;

    void *p_ti, *p_tw, *p_g, *p_u, *p_h, *p_ob, *p_gs, *p_us, *p_hs, *p_ys;
    cudaGetSymbolAddress(&p_ti, g_topk_i);  cudaGetSymbolAddress(&p_tw, g_topk_w);
    cudaGetSymbolAddress(&p_g,  g_gbuf);    cudaGetSymbolAddress(&p_u,  g_ubuf);
    cudaGetSymbolAddress(&p_h,  g_hbuf);    cudaGetSymbolAddress(&p_ob, g_outb);
    cudaGetSymbolAddress(&p_gs, g_gs);      cudaGetSymbolAddress(&p_us, g_us);
    cudaGetSymbolAddress(&p_hs, g_hs);      cudaGetSymbolAddress(&p_ys, g_ys);

    cudaFuncSetAttribute(fg_gemm<true>,  cudaFuncAttributeMaxDynamicSharedMemorySize, SMEM_TOT);
    cudaFuncSetAttribute(fg_gemm<false>, cudaFuncAttributeMaxDynamicSharedMemorySize, SMEM_TOT);

    // 1) gate + dispatch
    gate_kernel<<<TT, 64>>>(x, gw, (int*)p_ti, (float*)p_tw);
    zero_cnt_kernel<<<1, 64>>>();
    dispatch_kernel<<<(NPAIR + 255)/256, 256>>>((const int*)p_ti);

    // 2) routed GEMM1: g and u (A = gathered x rows fp32, K = HH)
    fg_gemm<true><<<dim3(MM/128, CC/128, EE), 256, SMEM_TOT>>>(
        x, Wg, (float*)p_g, HH, KK, (long long)MM*HH, MM, 0);
    fg_gemm<true><<<dim3(MM/128, CC/128, EE), 256, SMEM_TOT>>>(
        x, Wu, (float*)p_u, HH, KK, (long long)MM*HH, MM, 0);

    // 3) swiglu -> h (fp32)
    {
        size_t n4 = (size_t)NPAIR*MM/4;
        swiglu_kernel<<<(int)((n4 + 255)/256), 256>>>((const float*)p_g, (const float*)p_u,
                                                      (float*)p_h, n4);
    }

    // 4) routed GEMM2 (Wd): A = h rows by pair id, K = MM
    fg_gemm<true><<<dim3(HH/128, CC/128, EE), 256, SMEM_TOT>>>(
        (const float*)p_h, Wd, (float*)p_ob, MM, 1, (long long)HH*MM, HH, 0);

    // 5) shared expert g,u (K = HH)
    fg_gemm<false><<<dim3(MSS/128, TT/128, 1), 256, SMEM_TOT>>>(
        x, Sg, (float*)p_gs, HH, 1, 0LL, MSS, TT);
    fg_gemm<false><<<dim3(MSS/128, TT/128, 1), 256, SMEM_TOT>>>(
        x, Su, (float*)p_us, HH, 1, 0LL, MSS, TT);

    // 6) shared swiglu
    {
        size_t n4 = (size_t)TT*MSS/4;
        swiglu_kernel<<<(int)((n4 + 255)/256), 256>>>((const float*)p_gs, (const float*)p_us,
                                                      (float*)p_hs, n4);
    }

    // 7) shared GEMM2 (Sd, K = MSS)
    fg_gemm<false><<<dim3(HH/128, TT/128, 1), 256, SMEM_TOT>>>(
        (const float*)p_hs, Sd, (float*)p_ys, MSS, 1, 0LL, HH, TT);

    // 8) combine
    combine_kernel<<<TT, 256>>>((const float*)p_ob, (const float*)p_ys,
                                (const float*)p_tw, y);
}

// round 14
// speedup vs baseline: 1.6914x; 1.4881x over previous
#include <cuda_runtime.h>
#include <cuda_bf16.h>
#include <math.h>
#include <stdint.h>

// ---------------- problem constants ----------------
#define TT   4096
#define HH   2048
#define EE   64
#define MM   1408
#define MSS  2816
#define KK   6
#define CC   768
#define NGG  8
#define TGG  3
#define NPAIR (TT*KK)        // 24576
#define GTOK 4               // tokens per gate block

// ---------------- device scratch ----------------
__device__ int   g_topk_i[NPAIR];
__device__ float g_topk_w[NPAIR];
__device__ int   g_cnt[EE];
__device__ int   g_lists[EE*CC];
__device__ float g_gbuf[(size_t)NPAIR*MM];
__device__ float g_hbuf[(size_t)NPAIR*MM];
__device__ float g_outb[(size_t)NPAIR*HH];
__device__ float g_gs[(size_t)TT*MSS];
__device__ float g_hs[(size_t)TT*MSS];
__device__ float g_ys[(size_t)TT*HH];

// ---------------- gate: 4 tokens/block, coalesced gw streaming ----------------
__global__ void __launch_bounds__(256)
gate_kernel(const float* __restrict__ x,
            const float* __restrict__ gw,
            int* __restrict__ ti, float* __restrict__ tw)
{
    const int tb = blockIdx.x * GTOK;
    __shared__ float xs[GTOK][HH];
    __shared__ float sc[GTOK][EE];
    const int tid = threadIdx.x;
    for (int i = tid; i < GTOK*HH; i += 256){
        int tl = i >> 11, h = i & (HH-1);
        xs[tl][h] = x[(size_t)(tb+tl)*HH + h];
    }
    __syncthreads();
    {
        const int w = tid >> 5, lane = tid & 31;
        for (int e8 = 0; e8 < 8; ++e8){
            int e = w*8 + e8;
            const float* wrow = gw + (size_t)e*HH;
            float a0=0.f, a1=0.f, a2=0.f, a3=0.f;
            for (int h = lane; h < HH; h += 32){
                float wv = wrow[h];
                a0 = fmaf(xs[0][h], wv, a0);
                a1 = fmaf(xs[1][h], wv, a1);
                a2 = fmaf(xs[2][h], wv, a2);
                a3 = fmaf(xs[3][h], wv, a3);
            }
            #pragma unroll
            for (int off = 16; off; off >>= 1){
                a0 += __shfl_xor_sync(0xFFFFFFFFu, a0, off);
                a1 += __shfl_xor_sync(0xFFFFFFFFu, a1, off);
                a2 += __shfl_xor_sync(0xFFFFFFFFu, a2, off);
                a3 += __shfl_xor_sync(0xFFFFFFFFu, a3, off);
            }
            if (lane == 0){
                sc[0][e] = a0; sc[1][e] = a1; sc[2][e] = a2; sc[3][e] = a3;
            }
        }
    }
    __syncthreads();
    if (tid < GTOK){
        float* scp = sc[tid];
        const int t = tb + tid;
        float mx = scp[0];
        for (int e = 1; e < EE; ++e) mx = fmaxf(mx, scp[e]);
        float sum = 0.f;
        for (int e = 0; e < EE; ++e) { float v = expf(scp[e] - mx); scp[e] = v; sum += v; }
        float inv = 1.f / sum;
        for (int e = 0; e < EE; ++e) scp[e] *= inv;
        float gs[NGG];
        for (int g = 0; g < NGG; ++g) {
            float m = scp[g*8];
            for (int j = 1; j < 8; ++j) m = fmaxf(m, scp[g*8 + j]);
            gs[g] = m;
        }
        unsigned gsel = 0;
        for (int it = 0; it < TGG; ++it) {
            int best = -1; float bv = -1e30f;
            for (int g = 0; g < NGG; ++g)
                if (!((gsel >> g) & 1u) && gs[g] > bv) { bv = gs[g]; best = g; }
            gsel |= 1u << best;
        }
        unsigned long long used = 0ull;
        for (int kk = 0; kk < KK; ++kk) {
            int best = -1; float bv = -1e30f;
            for (int e = 0; e < EE; ++e) {
                if (!((gsel >> (e >> 3)) & 1u)) continue;
                if ((used >> e) & 1ull) continue;
                if (scp[e] > bv) { bv = scp[e]; best = e; }
            }
            used |= 1ull << best;
            ti[t*KK + kk] = best;
            tw[t*KK + kk] = scp[best];
        }
    }
}

__global__ void zero_cnt_kernel() { if (threadIdx.x < EE) g_cnt[threadIdx.x] = 0; }

__global__ void dispatch_kernel(const int* __restrict__ ti)
{
    int p = blockIdx.x * blockDim.x + threadIdx.x;
    if (p >= NPAIR) return;
    int e = ti[p];
    int r = atomicAdd(&g_cnt[e], 1);
    if (r < CC) g_lists[e*CC + r] = p;
}

// ======================= single-pass tf32 MMA GEMM =========
// CTA 128x128, k-chunk 32 (4 k-steps of 8), 256 threads (8 warps of 64x32),
// 2-stage smem, fused fp32->tf32 in the loader, 2 CTAs/SM.
// FUSE: epilogue computes silu(Gsrc)*acc (fused SwiGLU for the u-projection).

#define LDSM4(R, addr) asm volatile( \
    "ldmatrix.sync.aligned.m8n8.x4.shared.b16 {%0,%1,%2,%3},[%4];" \
    : "=r"((R)[0]), "=r"((R)[1]), "=r"((R)[2]), "=r"((R)[3]) : "r"(addr))
#define MMAT(C, A, B) asm volatile( \
    "mma.sync.aligned.m16n8k8.row.col.f32.tf32.tf32.f32 " \
    "{%0,%1,%2,%3},{%4,%5,%6,%7},{%8,%9},{%0,%1,%2,%3};" \
    : "+f"((C)[0]), "+f"((C)[1]), "+f"((C)[2]), "+f"((C)[3]) \
    : "r"((A)[0]), "r"((A)[1]), "r"((A)[2]), "r"((A)[3]), "r"((B)[0]), "r"((B)[1]))

// row pitch 144B (32 fp32 + 16B pad -> conflict-free ldmatrix), A at 0, B at 18432
#define PITCH   144
#define B_BASE  18432
#define STAGE_B 36864
#define SMEM_TOT (2*STAGE_B + 1024)

__device__ __forceinline__ uint32_t f2tf(float x){
    uint32_t u; asm("cvt.rna.tf32.f32 %0, %1;" : "=r"(u) : "f"(x)); return u;
}
__device__ __forceinline__ uint4 cvt4(float4 v){
    return make_uint4(f2tf(v.x), f2tf(v.y), f2tf(v.z), f2tf(v.w));
}
__device__ __forceinline__ float silu_mul(float g, float u){
    return (g / (1.f + expf(-g))) * u;
}

template<bool GATHER, bool FUSE>
__global__ void __launch_bounds__(256, 2)
fg_gemm(const float* __restrict__ A,
        const float* __restrict__ Bg,
        float* __restrict__ Out,
        const float* __restrict__ Gsrc,
        int Kd, int adiv, long long bstride, int ldo, int nrows_fixed)
{
    extern __shared__ char smem[];
    const int e = blockIdx.z;
    int nrows; const int* mylist = nullptr;
    if (GATHER){ nrows = min(g_cnt[e], CC); mylist = &g_lists[e*CC]; }
    else nrows = nrows_fixed;
    const int m0 = blockIdx.y*128;
    if (m0 >= nrows) return;
    const int n0 = blockIdx.x*128;
    const float* B = Bg + (size_t)e*bstride;

    int* rowA = (int*)(smem + 2*STAGE_B);
    int* rowO = (int*)(smem + 2*STAGE_B + 512);
    const int tid = threadIdx.x;
    if (tid < 128){
        int r = m0 + tid;
        if (r < nrows){
            if (GATHER){ int p = mylist[r]; rowA[tid] = p/adiv; rowO[tid] = p; }
            else       { rowA[tid] = r;      rowO[tid] = r; }
        } else { rowA[tid] = -1; rowO[tid] = -1; }
    }
    __syncthreads();

    // loaders: lrow = tid>>1 (0..127), half = tid&1 (16 floats each)
    const int lrow = tid >> 1, half = tid & 1;
    int ra = rowA[lrow]; if (ra < 0) ra = 0;
    const float* pa = A + (size_t)ra*Kd;
    const float* pb = B + (size_t)(n0 + lrow)*Kd;
    char* sa = smem + lrow*PITCH;
    char* sb = smem + B_BASE + lrow*PITCH;

    float4 s0, s1, s2, s3;     // shared 16-float staging
    auto ldg16 = [&](const float* p, int kf){
        s0 = *(const float4*)(p + kf);
        s1 = *(const float4*)(p + kf + 4);
        s2 = *(const float4*)(p + kf + 8);
        s3 = *(const float4*)(p + kf + 12);
    };
    auto sts16 = [&](char* d, int buf){
        char* dd = d + buf*STAGE_B + half*64;
        *(uint4*)(dd)      = cvt4(s0);
        *(uint4*)(dd + 16) = cvt4(s1);
        *(uint4*)(dd + 32) = cvt4(s2);
        *(uint4*)(dd + 48) = cvt4(s3);
    };
    const int hofs = half*16;

    const int lane = tid & 31;
    const int wid  = tid >> 5;
    const int wm = (wid & 1) * 64;       // warp tile 64x32
    const int wn = (wid >> 1) * 32;

    float acc[4][4][4];
    #pragma unroll
    for (int i = 0; i < 4; ++i)
        #pragma unroll
        for (int j = 0; j < 4; ++j)
            #pragma unroll
            for (int c = 0; c < 4; ++c) acc[i][j][c] = 0.f;

    const uint32_t smem_u = (uint32_t)__cvta_generic_to_shared(smem);
    const uint32_t aoff = (uint32_t)((wm + (lane & 15)) * PITCH + (lane >> 4) * 16);
    const uint32_t boff = (uint32_t)(B_BASE
        + (wn + (lane & 7) + (lane >> 4) * 8) * PITCH + ((lane >> 3) & 1) * 16);

    // one k-step (k=8): 6x LDSM4 + 16 MMA
    auto mma_ks = [&](uint32_t b, int ks){
        const uint32_t ko = ks * 32;
        uint32_t af[4][4], bf[2][4];
        LDSM4(bf[0], b + boff + ko);            // n-tiles 0,1
        LDSM4(bf[1], b + boff + 2304 + ko);     // n-tiles 2,3 (16 rows * 144B)
        #pragma unroll
        for (int mi = 0; mi < 4; ++mi)
            LDSM4(af[mi], b + aoff + mi*2304 + ko);
        #pragma unroll
        for (int mi = 0; mi < 4; ++mi)
            #pragma unroll
            for (int ni = 0; ni < 4; ++ni)
                MMAT(acc[mi][ni], af[mi], (&bf[ni>>1][(ni&1)*2]));
    };

    const int KT = Kd / 32;
    // prologue: fill stage 0
    ldg16(pa, hofs);      sts16(sa, 0);
    ldg16(pb, hofs);      sts16(sb, 0);

    for (int kt = 0; kt < KT; ++kt){
        __syncthreads();
        const uint32_t b = smem_u + (kt & 1) * STAGE_B;
        const int nb = (kt + 1) & 1;
        const bool more = (kt + 1 < KT);
        const int kn = (kt + 1) * 32 + hofs;
        if (more) ldg16(pa, kn);
        mma_ks(b, 0);
        mma_ks(b, 1);
        if (more){ sts16(sa, nb); ldg16(pb, kn); }
        mma_ks(b, 2);
        if (more) sts16(sb, nb);
        mma_ks(b, 3);
    }

    // epilogue (optionally fused SwiGLU: Out = silu(Gsrc)*acc)
    const int g4 = lane >> 2, tig = lane & 3;
    #pragma unroll
    for (int mi = 0; mi < 4; ++mi){
        int r0 = wm + mi*16 + g4;
        int r1 = r0 + 8;
        int o0 = rowO[r0], o1 = rowO[r1];
        #pragma unroll
        for (int ni = 0; ni < 4; ++ni){
            int cc = n0 + wn + ni*8 + tig*2;
            if (o0 >= 0){
                float2 v = make_float2(acc[mi][ni][0], acc[mi][ni][1]);
                if (FUSE){
                    float2 gv = *(const float2*)(Gsrc + (size_t)o0*ldo + cc);
                    v.x = silu_mul(gv.x, v.x);
                    v.y = silu_mul(gv.y, v.y);
                }
                *(float2*)(Out + (size_t)o0*ldo + cc) = v;
            }
            if (o1 >= 0){
                float2 v = make_float2(acc[mi][ni][2], acc[mi][ni][3]);
                if (FUSE){
                    float2 gv = *(const float2*)(Gsrc + (size_t)o1*ldo + cc);
                    v.x = silu_mul(gv.x, v.x);
                    v.y = silu_mul(gv.y, v.y);
                }
                *(float2*)(Out + (size_t)o1*ldo + cc) = v;
            }
        }
    }
}

// ---------------- combine ----------------
__global__ void combine_kernel(const float* __restrict__ ob,
                               const float* __restrict__ ys,
                               const float* __restrict__ tw,
                               float* __restrict__ y)
{
    int t = blockIdx.x;
    for (int c = threadIdx.x; c < HH; c += blockDim.x) {
        float acc = ys[(size_t)t*HH + c];
        #pragma unroll
        for (int k = 0; k < KK; ++k) {
            int p = t*KK + k;
            acc = fmaf(tw[p], ob[(size_t)p*HH + c], acc);
        }
        y[(size_t)t*HH + c] = acc;
    }
}

// ---------------- launch ----------------
extern "C" void kernel_launch(void* const* d_in, const int* in_sizes, int n_in,
                              void* d_out, int out_size)
{
    const float* x  = (const float*)d_in[0];
    const float* gw = (const float*)d_in[1];
    const float* Wg = (const float*)d_in[2];
    const float* Wu = (const float*)d_in[3];
    const float* Wd = (const float*)d_in[4];
    const float* Sg = (const float*)d_in[5];
    const float* Su = (const float*)d_in[6];
    const float* Sd = (const float*)d_in[7];
    float* y = (float*)d_out;

    void *p_ti, *p_tw, *p_g, *p_h, *p_ob, *p_gs, *p_hs, *p_ys;
    cudaGetSymbolAddress(&p_ti, g_topk_i);  cudaGetSymbolAddress(&p_tw, g_topk_w);
    cudaGetSymbolAddress(&p_g,  g_gbuf);    cudaGetSymbolAddress(&p_h,  g_hbuf);
    cudaGetSymbolAddress(&p_ob, g_outb);
    cudaGetSymbolAddress(&p_gs, g_gs);      cudaGetSymbolAddress(&p_hs, g_hs);
    cudaGetSymbolAddress(&p_ys, g_ys);

    cudaFuncSetAttribute(fg_gemm<true,false>,  cudaFuncAttributeMaxDynamicSharedMemorySize, SMEM_TOT);
    cudaFuncSetAttribute(fg_gemm<true,true>,   cudaFuncAttributeMaxDynamicSharedMemorySize, SMEM_TOT);
    cudaFuncSetAttribute(fg_gemm<false,false>, cudaFuncAttributeMaxDynamicSharedMemorySize, SMEM_TOT);
    cudaFuncSetAttribute(fg_gemm<false,true>,  cudaFuncAttributeMaxDynamicSharedMemorySize, SMEM_TOT);

    // 1) gate + dispatch
    gate_kernel<<<TT/GTOK, 256>>>(x, gw, (int*)p_ti, (float*)p_tw);
    zero_cnt_kernel<<<1, 64>>>();
    dispatch_kernel<<<(NPAIR + 255)/256, 256>>>((const int*)p_ti);

    // 2) routed GEMM1-g (A = gathered x rows fp32, K = HH) -> g
    fg_gemm<true,false><<<dim3(MM/128, CC/128, EE), 256, SMEM_TOT>>>(
        x, Wg, (float*)p_g, nullptr, HH, KK, (long long)MM*HH, MM, 0);
    // 3) routed GEMM1-u with fused SwiGLU -> h = silu(g)*u
    fg_gemm<true,true><<<dim3(MM/128, CC/128, EE), 256, SMEM_TOT>>>(
        x, Wu, (float*)p_h, (const float*)p_g, HH, KK, (long long)MM*HH, MM, 0);

    // 4) routed GEMM2 (Wd): A = h rows by pair id, K = MM
    fg_gemm<true,false><<<dim3(HH/128, CC/128, EE), 256, SMEM_TOT>>>(
        (const float*)p_h, Wd, (float*)p_ob, nullptr, MM, 1, (long long)HH*MM, HH, 0);

    // 5) shared expert g, then u with fused SwiGLU (K = HH)
    fg_gemm<false,false><<<dim3(MSS/128, TT/128, 1), 256, SMEM_TOT>>>(
        x, Sg, (float*)p_gs, nullptr, HH, 1, 0LL, MSS, TT);
    fg_gemm<false,true><<<dim3(MSS/128, TT/128, 1), 256, SMEM_TOT>>>(
        x, Su, (float*)p_hs, (const float*)p_gs, HH, 1, 0LL, MSS, TT);

    // 6) shared GEMM2 (Sd, K = MSS)
    fg_gemm<false,false><<<dim3(HH/128, TT/128, 1), 256, SMEM_TOT>>>(
        (const float*)p_hs, Sd, (float*)p_ys, nullptr, MSS, 1, 0LL, HH, TT);

    // 7) combine
    combine_kernel<<<TT, 256>>>((const float*)p_ob, (const float*)p_ys,
                                (const float*)p_tw, y);
}

// round 15
// speedup vs baseline: 1.7870x; 1.0565x over previous
#include <cuda_runtime.h>
#include <cuda_bf16.h>
#include <math.h>
#include <stdint.h>

// ---------------- problem constants ----------------
#define TT   4096
#define HH   2048
#define EE   64
#define MM   1408
#define MSS  2816
#define KK   6
#define CC   768
#define NGG  8
#define TGG  3
#define NPAIR (TT*KK)        // 24576
#define GTOK 4               // tokens per gate block

// ---------------- device scratch ----------------
__device__ int   g_topk_i[NPAIR];
__device__ float g_topk_w[NPAIR];
__device__ int   g_cnt[EE];
__device__ int   g_lists[EE*CC];
__device__ float g_gbuf[(size_t)NPAIR*MM];
__device__ float g_hbuf[(size_t)NPAIR*MM];
__device__ float g_outb[(size_t)NPAIR*HH];
__device__ float g_gs[(size_t)TT*MSS];
__device__ float g_hs[(size_t)TT*MSS];
__device__ float g_ys[(size_t)TT*HH];

// ---------------- gate: 4 tokens/block, coalesced gw streaming ----------------
__global__ void __launch_bounds__(256)
gate_kernel(const float* __restrict__ x,
            const float* __restrict__ gw,
            int* __restrict__ ti, float* __restrict__ tw)
{
    const int tb = blockIdx.x * GTOK;
    __shared__ float xs[GTOK][HH];
    __shared__ float sc[GTOK][EE];
    const int tid = threadIdx.x;
    for (int i = tid; i < GTOK*HH; i += 256){
        int tl = i >> 11, h = i & (HH-1);
        xs[tl][h] = x[(size_t)(tb+tl)*HH + h];
    }
    __syncthreads();
    {
        const int w = tid >> 5, lane = tid & 31;
        for (int e8 = 0; e8 < 8; ++e8){
            int e = w*8 + e8;
            const float* wrow = gw + (size_t)e*HH;
            float a0=0.f, a1=0.f, a2=0.f, a3=0.f;
            for (int h = lane; h < HH; h += 32){
                float wv = wrow[h];
                a0 = fmaf(xs[0][h], wv, a0);
                a1 = fmaf(xs[1][h], wv, a1);
                a2 = fmaf(xs[2][h], wv, a2);
                a3 = fmaf(xs[3][h], wv, a3);
            }
            #pragma unroll
            for (int off = 16; off; off >>= 1){
                a0 += __shfl_xor_sync(0xFFFFFFFFu, a0, off);
                a1 += __shfl_xor_sync(0xFFFFFFFFu, a1, off);
                a2 += __shfl_xor_sync(0xFFFFFFFFu, a2, off);
                a3 += __shfl_xor_sync(0xFFFFFFFFu, a3, off);
            }
            if (lane == 0){
                sc[0][e] = a0; sc[1][e] = a1; sc[2][e] = a2; sc[3][e] = a3;
            }
        }
    }
    __syncthreads();
    if (tid < GTOK){
        float* scp = sc[tid];
        const int t = tb + tid;
        float mx = scp[0];
        for (int e = 1; e < EE; ++e) mx = fmaxf(mx, scp[e]);
        float sum = 0.f;
        for (int e = 0; e < EE; ++e) { float v = expf(scp[e] - mx); scp[e] = v; sum += v; }
        float inv = 1.f / sum;
        for (int e = 0; e < EE; ++e) scp[e] *= inv;
        float gs[NGG];
        for (int g = 0; g < NGG; ++g) {
            float m = scp[g*8];
            for (int j = 1; j < 8; ++j) m = fmaxf(m, scp[g*8 + j]);
            gs[g] = m;
        }
        unsigned gsel = 0;
        for (int it = 0; it < TGG; ++it) {
            int best = -1; float bv = -1e30f;
            for (int g = 0; g < NGG; ++g)
                if (!((gsel >> g) & 1u) && gs[g] > bv) { bv = gs[g]; best = g; }
            gsel |= 1u << best;
        }
        unsigned long long used = 0ull;
        for (int kk = 0; kk < KK; ++kk) {
            int best = -1; float bv = -1e30f;
            for (int e = 0; e < EE; ++e) {
                if (!((gsel >> (e >> 3)) & 1u)) continue;
                if ((used >> e) & 1ull) continue;
                if (scp[e] > bv) { bv = scp[e]; best = e; }
            }
            used |= 1ull << best;
            ti[t*KK + kk] = best;
            tw[t*KK + kk] = scp[best];
        }
    }
}

__global__ void zero_cnt_kernel() { if (threadIdx.x < EE) g_cnt[threadIdx.x] = 0; }

__global__ void dispatch_kernel(const int* __restrict__ ti)
{
    int p = blockIdx.x * blockDim.x + threadIdx.x;
    if (p >= NPAIR) return;
    int e = ti[p];
    int r = atomicAdd(&g_cnt[e], 1);
    if (r < CC) g_lists[e*CC + r] = p;
}

// ======================= hybrid tf32 MMA GEMM =========
// CTA 128x128, k-chunk 32 (4 k-steps of 8), 256 threads (8 warps of 64x32).
// A: LDG -> cvt(tf32) -> STS, 2-stage (register staging, loader-side cvt).
// B: cp.async.cg raw fp32, 3-stage ring, fragment-side cvt.
// 2 CTAs/SM. FUSE: epilogue computes silu(Gsrc)*acc.

#define LDSM4(R, addr) asm volatile( \
    "ldmatrix.sync.aligned.m8n8.x4.shared.b16 {%0,%1,%2,%3},[%4];" \
    : "=r"((R)[0]), "=r"((R)[1]), "=r"((R)[2]), "=r"((R)[3]) : "r"(addr))
#define MMAT(C, A, B) asm volatile( \
    "mma.sync.aligned.m16n8k8.row.col.f32.tf32.tf32.f32 " \
    "{%0,%1,%2,%3},{%4,%5,%6,%7},{%8,%9},{%0,%1,%2,%3};" \
    : "+f"((C)[0]), "+f"((C)[1]), "+f"((C)[2]), "+f"((C)[3]) \
    : "r"((A)[0]), "r"((A)[1]), "r"((A)[2]), "r"((A)[3]), "r"((B)[0]), "r"((B)[1]))

// row pitch 144B (32 fp32 + 16B pad -> conflict-free ldmatrix)
#define PITCH   144
#define AST     18432              // one A stage: 128 rows * 144B
#define B_BASE  (2*AST)            // 36864
#define BST     18432              // one B stage
#define NBSTG   3
#define META_O  (B_BASE + NBSTG*BST)   // 92160
#define SMEM_TOT (META_O + 1024)

__device__ __forceinline__ uint32_t f2tf(float x){
    uint32_t u; asm("cvt.rna.tf32.f32 %0, %1;" : "=r"(u) : "f"(x)); return u;
}
__device__ __forceinline__ uint4 cvt4(float4 v){
    return make_uint4(f2tf(v.x), f2tf(v.y), f2tf(v.z), f2tf(v.w));
}
__device__ __forceinline__ uint32_t tfr(uint32_t x){
    uint32_t r; asm("cvt.rna.tf32.f32 %0, %1;" : "=r"(r) : "f"(__uint_as_float(x)));
    return r;
}
__device__ __forceinline__ void cp16(uint32_t dst, const void* src){
    asm volatile("cp.async.cg.shared.global [%0], [%1], 16;"
                 :: "r"(dst), "l"(src));
}
__device__ __forceinline__ float silu_mul(float g, float u){
    return (g / (1.f + expf(-g))) * u;
}

template<bool GATHER, bool FUSE>
__global__ void __launch_bounds__(256, 2)
fg_gemm(const float* __restrict__ A,
        const float* __restrict__ Bg,
        float* __restrict__ Out,
        const float* __restrict__ Gsrc,
        int Kd, int adiv, long long bstride, int ldo, int nrows_fixed)
{
    extern __shared__ char smem[];
    const int e = blockIdx.z;
    int nrows; const int* mylist = nullptr;
    if (GATHER){ nrows = min(g_cnt[e], CC); mylist = &g_lists[e*CC]; }
    else nrows = nrows_fixed;
    const int m0 = blockIdx.y*128;
    if (m0 >= nrows) return;
    const int n0 = blockIdx.x*128;
    const float* B = Bg + (size_t)e*bstride;

    int* rowA = (int*)(smem + META_O);
    int* rowO = (int*)(smem + META_O + 512);
    const int tid = threadIdx.x;
    if (tid < 128){
        int r = m0 + tid;
        if (r < nrows){
            if (GATHER){ int p = mylist[r]; rowA[tid] = p/adiv; rowO[tid] = p; }
            else       { rowA[tid] = r;      rowO[tid] = r; }
        } else { rowA[tid] = -1; rowO[tid] = -1; }
    }
    __syncthreads();

    const uint32_t smem_u = (uint32_t)__cvta_generic_to_shared(smem);

    // loader mapping: lrow = tid>>1 (0..127), half = tid&1 (16 floats each)
    const int lrow = tid >> 1, half = tid & 1;
    int ra = rowA[lrow]; if (ra < 0) ra = 0;
    const float* pa = A + (size_t)ra*Kd;
    const float* pb = B + (size_t)(n0 + lrow)*Kd + half*16;
    char* sa = smem + lrow*PITCH;
    const uint32_t sb_u = smem_u + B_BASE + lrow*PITCH + half*64;
    const int hofs = half*16;

    // A path: register staging + loader-side cvt
    float4 s0, s1, s2, s3;
    auto ldgA = [&](int kf){
        s0 = *(const float4*)(pa + kf);
        s1 = *(const float4*)(pa + kf + 4);
        s2 = *(const float4*)(pa + kf + 8);
        s3 = *(const float4*)(pa + kf + 12);
    };
    auto stsA = [&](int buf){
        char* dd = sa + buf*AST + half*64;
        *(uint4*)(dd)      = cvt4(s0);
        *(uint4*)(dd + 16) = cvt4(s1);
        *(uint4*)(dd + 32) = cvt4(s2);
        *(uint4*)(dd + 48) = cvt4(s3);
    };
    // B path: cp.async raw fp32, one commit group per chunk
    auto cpB = [&](int stg, int kt){
        const float* q = pb + kt*32;
        const uint32_t d = sb_u + stg*BST;
        #pragma unroll
        for (int j = 0; j < 4; ++j)
            cp16(d + j*16, q + j*4);
        asm volatile("cp.async.commit_group;" ::);
    };

    const int lane = tid & 31;
    const int wid  = tid >> 5;
    const int wm = (wid & 1) * 64;       // warp tile 64x32
    const int wn = (wid >> 1) * 32;

    float acc[4][4][4];
    #pragma unroll
    for (int i = 0; i < 4; ++i)
        #pragma unroll
        for (int j = 0; j < 4; ++j)
            #pragma unroll
            for (int c = 0; c < 4; ++c) acc[i][j][c] = 0.f;

    const uint32_t aoff = (uint32_t)((wm + (lane & 15)) * PITCH + (lane >> 4) * 16);
    const uint32_t boff = (uint32_t)(B_BASE
        + (wn + (lane & 7) + (lane >> 4) * 8) * PITCH + ((lane >> 3) & 1) * 16);

    // one k-step (k=8): 6x LDSM4 + 8 cvt(B frags) + 16 MMA
    auto mma_ks = [&](uint32_t bA, int bstg, int ks){
        const uint32_t ko = ks * 32;
        const uint32_t bB = smem_u + bstg*BST;
        uint32_t af[4][4], bf[2][4];
        LDSM4(bf[0], bB + boff + ko);            // n-tiles 0,1
        LDSM4(bf[1], bB + boff + 2304 + ko);     // n-tiles 2,3
        #pragma unroll
        for (int mi = 0; mi < 4; ++mi)
            LDSM4(af[mi], bA + aoff + mi*2304 + ko);
        #pragma unroll
        for (int i = 0; i < 2; ++i)
            #pragma unroll
            for (int j = 0; j < 4; ++j) bf[i][j] = tfr(bf[i][j]);
        #pragma unroll
        for (int mi = 0; mi < 4; ++mi)
            #pragma unroll
            for (int ni = 0; ni < 4; ++ni)
                MMAT(acc[mi][ni], af[mi], (&bf[ni>>1][(ni&1)*2]));
    };

    const int KT = Kd / 32;
    // prologue: B stages 0,1 in flight; A stage 0 filled
    cpB(0, 0);
    if (KT > 1) cpB(1, 1);
    ldgA(hofs); stsA(0);

    int bstg = 0;
    for (int kt = 0; kt < KT; ++kt){
        if (kt + 1 < KT) asm volatile("cp.async.wait_group 1;" ::);
        else             asm volatile("cp.async.wait_group 0;" ::);
        __syncthreads();
        // prefetch B for kt+2 into the ring slot consumed at kt-1 (safe past barrier)
        if (kt + 2 < KT){
            int ns = bstg + 2; if (ns >= NBSTG) ns -= NBSTG;
            cpB(ns, kt + 2);
        }
        const uint32_t bA = smem_u + (kt & 1) * AST;
        const bool more = (kt + 1 < KT);
        if (more) ldgA((kt + 1) * 32 + hofs);
        mma_ks(bA, bstg, 0);
        mma_ks(bA, bstg, 1);
        if (more) stsA((kt + 1) & 1);
        mma_ks(bA, bstg, 2);
        mma_ks(bA, bstg, 3);
        if (++bstg == NBSTG) bstg = 0;
    }

    // epilogue (optionally fused SwiGLU: Out = silu(Gsrc)*acc)
    const int g4 = lane >> 2, tig = lane & 3;
    #pragma unroll
    for (int mi = 0; mi < 4; ++mi){
        int r0 = wm + mi*16 + g4;
        int r1 = r0 + 8;
        int o0 = rowO[r0], o1 = rowO[r1];
        #pragma unroll
        for (int ni = 0; ni < 4; ++ni){
            int cc = n0 + wn + ni*8 + tig*2;
            if (o0 >= 0){
                float2 v = make_float2(acc[mi][ni][0], acc[mi][ni][1]);
                if (FUSE){
                    float2 gv = *(const float2*)(Gsrc + (size_t)o0*ldo + cc);
                    v.x = silu_mul(gv.x, v.x);
                    v.y = silu_mul(gv.y, v.y);
                }
                *(float2*)(Out + (size_t)o0*ldo + cc) = v;
            }
            if (o1 >= 0){
                float2 v = make_float2(acc[mi][ni][2], acc[mi][ni][3]);
                if (FUSE){
                    float2 gv = *(const float2*)(Gsrc + (size_t)o1*ldo + cc);
                    v.x = silu_mul(gv.x, v.x);
                    v.y = silu_mul(gv.y, v.y);
                }
                *(float2*)(Out + (size_t)o1*ldo + cc) = v;
            }
        }
    }
}

// ---------------- combine ----------------
__global__ void combine_kernel(const float* __restrict__ ob,
                               const float* __restrict__ ys,
                               const float* __restrict__ tw,
                               float* __restrict__ y)
{
    int t = blockIdx.x;
    for (int c = threadIdx.x; c < HH; c += blockDim.x) {
        float acc = ys[(size_t)t*HH + c];
        #pragma unroll
        for (int k = 0; k < KK; ++k) {
            int p = t*KK + k;
            acc = fmaf(tw[p], ob[(size_t)p*HH + c], acc);
        }
        y[(size_t)t*HH + c] = acc;
    }
}

// ---------------- launch ----------------
extern "C" void kernel_launch(void* const* d_in, const int* in_sizes, int n_in,
                              void* d_out, int out_size)
{
    const float* x  = (const float*)d_in[0];
    const float* gw = (const float*)d_in[1];
    const float* Wg = (const float*)d_in[2];
    const float* Wu = (const float*)d_in[3];
    const float* Wd = (const float*)d_in[4];
    const float* Sg = (const float*)d_in[5];
    const float* Su = (const float*)d_in[6];
    const float* Sd = (const float*)d_in[7];
    float* y = (float*)d_out;

    void *p_ti, *p_tw, *p_g, *p_h, *p_ob, *p_gs, *p_hs, *p_ys;
    cudaGetSymbolAddress(&p_ti, g_topk_i);  cudaGetSymbolAddress(&p_tw, g_topk_w);
    cudaGetSymbolAddress(&p_g,  g_gbuf);    cudaGetSymbolAddress(&p_h,  g_hbuf);
    cudaGetSymbolAddress(&p_ob, g_outb);
    cudaGetSymbolAddress(&p_gs, g_gs);      cudaGetSymbolAddress(&p_hs, g_hs);
    cudaGetSymbolAddress(&p_ys, g_ys);

    cudaFuncSetAttribute(fg_gemm<true,false>,  cudaFuncAttributeMaxDynamicSharedMemorySize, SMEM_TOT);
    cudaFuncSetAttribute(fg_gemm<true,true>,   cudaFuncAttributeMaxDynamicSharedMemorySize, SMEM_TOT);
    cudaFuncSetAttribute(fg_gemm<false,false>, cudaFuncAttributeMaxDynamicSharedMemorySize, SMEM_TOT);
    cudaFuncSetAttribute(fg_gemm<false,true>,  cudaFuncAttributeMaxDynamicSharedMemorySize, SMEM_TOT);

    // 1) gate + dispatch
    gate_kernel<<<TT/GTOK, 256>>>(x, gw, (int*)p_ti, (float*)p_tw);
    zero_cnt_kernel<<<1, 64>>>();
    dispatch_kernel<<<(NPAIR + 255)/256, 256>>>((const int*)p_ti);

    // 2) routed GEMM1-g (A = gathered x rows fp32, K = HH) -> g
    fg_gemm<true,false><<<dim3(MM/128, CC/128, EE), 256, SMEM_TOT>>>(
        x, Wg, (float*)p_g, nullptr, HH, KK, (long long)MM*HH, MM, 0);
    // 3) routed GEMM1-u with fused SwiGLU -> h = silu(g)*u
    fg_gemm<true,true><<<dim3(MM/128, CC/128, EE), 256, SMEM_TOT>>>(
        x, Wu, (float*)p_h, (const float*)p_g, HH, KK, (long long)MM*HH, MM, 0);

    // 4) routed GEMM2 (Wd): A = h rows by pair id, K = MM
    fg_gemm<true,false><<<dim3(HH/128, CC/128, EE), 256, SMEM_TOT>>>(
        (const float*)p_h, Wd, (float*)p_ob, nullptr, MM, 1, (long long)HH*MM, HH, 0);

    // 5) shared expert g, then u with fused SwiGLU (K = HH)
    fg_gemm<false,false><<<dim3(MSS/128, TT/128, 1), 256, SMEM_TOT>>>(
        x, Sg, (float*)p_gs, nullptr, HH, 1, 0LL, MSS, TT);
    fg_gemm<false,true><<<dim3(MSS/128, TT/128, 1), 256, SMEM_TOT>>>(
        x, Su, (float*)p_hs, (const float*)p_gs, HH, 1, 0LL, MSS, TT);

    // 6) shared GEMM2 (Sd, K = MSS)
    fg_gemm<false,false><<<dim3(HH/128, TT/128, 1), 256, SMEM_TOT>>>(
        (const float*)p_hs, Sd, (float*)p_ys, nullptr, MSS, 1, 0LL, HH, TT);

    // 7) combine
    combine_kernel<<<TT, 256>>>((const float*)p_ob, (const float*)p_ys,
                                (const float*)p_tw, y);
}